// round 2
// baseline (speedup 1.0000x reference)
#include <cuda_runtime.h>

#define NB 8
#define NC 96
#define NH 128
#define NW 128
#define EPSV 1e-5f
#define TW 32
#define WSTR 196   // padded duplicated-weight row stride (floats), 16B-aligned rows

// scratch (device globals: no allocation allowed)
__device__ float g_t [(size_t)NB * NC * NH * NW];   // 2x + vertical taps
__device__ float g_av[(size_t)NB * NC * NH * NW];   // x + vertical dwconv3
__device__ float g_out[(size_t)NB * NC * NH * NW];
__device__ float g_rowmean[NB * NC * NH];
__device__ float g_colmean[NB * NC * NW];
__device__ float g_ah[NB * NC * NH];
__device__ float g_aw[NB * NC * NW];

#define FMA2(d, a, b) asm("fma.rn.f32x2 %0, %1, %2, %0;" : "+l"(d) : "l"(a), "l"(b))
#define UNPACK2(lo, hi, v) asm("mov.b64 {%0,%1}, %2;" : "=f"(lo), "=f"(hi) : "l"(v))

// ---------------------------------------------------------------------------
// k_vert: per (b, c, w-tile): vertical 10-tap (merged) conv + vertical dwconv3
// ---------------------------------------------------------------------------
__global__ void __launch_bounds__(256)
k_vert(const float* __restrict__ x,
       const float* __restrict__ r_m, const float* __restrict__ wh_m,
       const float* __restrict__ r_l, const float* __restrict__ wh_l,
       const float* __restrict__ dg_wh)
{
    __shared__ float xt[NH * TW];           // 16 KB tile
    __shared__ int   moff[10];
    __shared__ float mfrac[10];
    __shared__ float wm[10];
    __shared__ float dgh[3];
    __shared__ int   snt;

    const int tid = threadIdx.x;
    const int wt  = blockIdx.x;             // 0..3
    const int c   = blockIdx.y;
    const int b   = blockIdx.z;

    if (tid == 0) {
        int mmap[10];
        int nt = 0;
        for (int j = 0; j < 10; j++) {
            float r  = fmaxf((j < 5 ? r_m[0] : r_l[0]), 1.0f);
            int   jo = (j < 5) ? (j - 2) : (j - 7);
            float sh = (float)jo * r;
            float f  = floorf(sh);
            int   off = (int)f;
            float fr  = sh - f;
            int slot = -1;
            for (int s = 0; s < nt; s++)
                if (moff[s] == off && mfrac[s] == fr) { slot = s; break; }
            if (slot < 0) { slot = nt++; moff[slot] = off; mfrac[slot] = fr; }
            mmap[j] = slot;
        }
        snt = nt;
        for (int s = 0; s < nt; s++) wm[s] = 0.0f;
        for (int j = 0; j < 10; j++)
            wm[mmap[j]] += (j < 5) ? wh_m[c * 5 + j] : wh_l[c * 5 + (j - 5)];
        dgh[0] = dg_wh[c * 3 + 0];
        dgh[1] = dg_wh[c * 3 + 1];
        dgh[2] = dg_wh[c * 3 + 2];
    }

    // load 128x32 tile (float4, coalesced)
    for (int i = tid; i < NH * TW / 4; i += 256) {
        int hh = i >> 3, w4 = i & 7;
        ((float4*)xt)[i] =
            ((const float4*)x)[((size_t)(b * NC + c) * NH + hh) * (NW / 4) + wt * (TW / 4) + w4];
    }
    __syncthreads();

    const int nt = snt;
    for (int i = tid; i < NH * TW; i += 256) {
        int h = i >> 5, w = i & (TW - 1);
        float xc = xt[h * TW + w];
        float tv = 2.0f * xc;
        for (int s = 0; s < nt; s++) {
            int hh = h + moff[s];
            float v = ((unsigned)hh < NH) ? xt[hh * TW + w] : 0.0f;
            float fr = mfrac[s];
            if (fr != 0.0f) {
                float v2 = ((unsigned)(hh + 1) < NH) ? xt[(hh + 1) * TW + w] : 0.0f;
                v = fmaf(fr, v2 - v, v);
            }
            tv = fmaf(wm[s], v, tv);
        }
        float up = (h > 0)      ? xt[(h - 1) * TW + w] : 0.0f;
        float dn = (h < NH - 1) ? xt[(h + 1) * TW + w] : 0.0f;
        float av = xc + dgh[0] * up + dgh[1] * xc + dgh[2] * dn;
        size_t gi = ((size_t)(b * NC + c) * NH + h) * NW + wt * TW + w;
        g_t[gi]  = tv;
        g_av[gi] = av;
    }
}

// ---------------------------------------------------------------------------
// k_main: per (b, h) row: finish s / anchor, 96x128x96 GEMM (f32x2), epilogue
// ---------------------------------------------------------------------------
// smem (floats): s_sm 12288 | a_sm 12288 | x_sm 12288 | wbuf 4704 | fSc/fBi/aA 288
#define SM_FLOATS (3 * NC * NW + 24 * WSTR + 3 * NC)

__global__ void __launch_bounds__(384, 1)
k_main(const float* __restrict__ x,
       const float* __restrict__ r_m,  const float* __restrict__ ww_m,
       const float* __restrict__ r_l,  const float* __restrict__ ww_l,
       const float* __restrict__ w_fuse,
       const float* __restrict__ bnf_g, const float* __restrict__ bnf_b,
       const float* __restrict__ bnf_m, const float* __restrict__ bnf_v,
       const float* __restrict__ dg_ww,
       const float* __restrict__ dg_g,  const float* __restrict__ dg_b,
       const float* __restrict__ dg_m,  const float* __restrict__ dg_v,
       const float* __restrict__ act_a)
{
    extern __shared__ float sm[];
    float* s_sm = sm;
    float* a_sm = sm + NC * NW;
    float* x_sm = sm + 2 * NC * NW;
    float* wbuf = sm + 3 * NC * NW;          // 4704 floats
    float* fSc  = sm + 3 * NC * NW + 24 * WSTR;
    float* fBi  = fSc + NC;
    float* aA   = fBi + NC;
    // phase-A params live inside wbuf (reused for GEMM weights later)
    float* wWm = wbuf;                       // NC*10 merged w-tap weights
    float* dgw = wbuf + NC * 10;             // NC*3
    float* aSc = dgw + NC * 3;               // NC
    float* aBi = aSc + NC;                   // NC

    __shared__ int   s_moff[10];
    __shared__ float s_mfrac[10];
    __shared__ int   s_map[10];
    __shared__ int   s_nt;

    const int tid = threadIdx.x;
    const int b = blockIdx.y;
    const int h = blockIdx.x;

    if (tid == 0) {
        int nt = 0;
        for (int j = 0; j < 10; j++) {
            float r  = fmaxf((j < 5 ? r_m[0] : r_l[0]), 1.0f);
            int   jo = (j < 5) ? (j - 2) : (j - 7);
            float sh = (float)jo * r;
            float f  = floorf(sh);
            int   off = (int)f;
            float fr  = sh - f;
            int slot = -1;
            for (int s = 0; s < nt; s++)
                if (s_moff[s] == off && s_mfrac[s] == fr) { slot = s; break; }
            if (slot < 0) { slot = nt++; s_moff[slot] = off; s_mfrac[slot] = fr; }
            s_map[j] = slot;
        }
        s_nt = nt;
    }
    __syncthreads();

    if (tid < NC) {
        float wm[10];
        #pragma unroll
        for (int s = 0; s < 10; s++) wm[s] = 0.0f;
        for (int j = 0; j < 10; j++)
            wm[s_map[j]] += (j < 5) ? ww_m[tid * 5 + j] : ww_l[tid * 5 + (j - 5)];
        #pragma unroll
        for (int s = 0; s < 10; s++) wWm[tid * 10 + s] = wm[s];

        float sA = dg_g[tid] * rsqrtf(dg_v[tid] + EPSV);
        aSc[tid] = sA;
        aBi[tid] = dg_b[tid] - sA * dg_m[tid];
        float sF = bnf_g[tid] * rsqrtf(bnf_v[tid] + EPSV);
        fSc[tid] = sF;
        fBi[tid] = bnf_b[tid] - sF * bnf_m[tid];
        aA[tid]  = act_a[tid];
    }
    for (int i = tid; i < NC * 3; i += 384) dgw[i] = dg_ww[i];

    // stage x row for all channels (float4, coalesced)
    for (int i = tid; i < NC * NW / 4; i += 384) {
        int ci = i >> 5, w4 = i & 31;
        ((float4*)x_sm)[i] =
            ((const float4*)x)[((size_t)(b * NC + ci) * NH + h) * (NW / 4) + w4];
    }
    __syncthreads();

    // ---- phase A: s = t + w-taps(x); anchor = BNfold(a_v + w-dwconv3(x)) ----
    const int nt = s_nt;
    for (int i = tid; i < NC * NW; i += 384) {
        int ci = i >> 7, w = i & (NW - 1);
        const float* xr = x_sm + ci * NW;
        float xc = xr[w];
        size_t gi = ((size_t)(b * NC + ci) * NH + h) * NW + w;
        float sv = g_t[gi];
        for (int s = 0; s < nt; s++) {
            int wp = w + s_moff[s];
            float v = ((unsigned)wp < NW) ? xr[wp] : 0.0f;
            float fr = s_mfrac[s];
            if (fr != 0.0f) {
                float v2 = ((unsigned)(wp + 1) < NW) ? xr[wp + 1] : 0.0f;
                v = fmaf(fr, v2 - v, v);
            }
            sv = fmaf(wWm[ci * 10 + s], v, sv);
        }
        s_sm[i] = sv;

        float lf = (w > 0)      ? xr[w - 1] : 0.0f;
        float rt = (w < NW - 1) ? xr[w + 1] : 0.0f;
        float e = dgw[ci * 3 + 0] * lf + dgw[ci * 3 + 1] * xc + dgw[ci * 3 + 2] * rt;
        a_sm[i] = fmaf(aSc[ci], g_av[gi] + e, aBi[ci]);
    }

    // ---- phase B: 96(o) x 128(p) x 96(k) GEMM, packed f32x2 ----
    const int lane = tid & 31;
    const int warp = tid >> 5;        // 12 warps, 8 outputs each
    const int ob = warp * 8;
    const int p = lane * 4;

    unsigned long long acc[8][2];
    #pragma unroll
    for (int i = 0; i < 8; i++) { acc[i][0] = 0ull; acc[i][1] = 0ull; }

    for (int c0 = 0; c0 < NC; c0 += 24) {
        __syncthreads();   // previous wbuf contents (params / prior chunk) done
        for (int i = tid; i < 24 * NC; i += 384) {
            int cl = i % 24, o = i / 24;
            float v = w_fuse[o * NC + c0 + cl];
            wbuf[cl * WSTR + 2 * o]     = v;   // duplicated pair for f32x2
            wbuf[cl * WSTR + 2 * o + 1] = v;
        }
        __syncthreads();
        #pragma unroll
        for (int cl = 0; cl < 24; cl++) {
            ulonglong2 sp = *(const ulonglong2*)(s_sm + (c0 + cl) * NW + p);
            const ulonglong2* wq = (const ulonglong2*)(wbuf + cl * WSTR + 2 * ob);
            ulonglong2 w0 = wq[0], w1 = wq[1], w2 = wq[2], w3 = wq[3];
            FMA2(acc[0][0], w0.x, sp.x); FMA2(acc[0][1], w0.x, sp.y);
            FMA2(acc[1][0], w0.y, sp.x); FMA2(acc[1][1], w0.y, sp.y);
            FMA2(acc[2][0], w1.x, sp.x); FMA2(acc[2][1], w1.x, sp.y);
            FMA2(acc[3][0], w1.y, sp.x); FMA2(acc[3][1], w1.y, sp.y);
            FMA2(acc[4][0], w2.x, sp.x); FMA2(acc[4][1], w2.x, sp.y);
            FMA2(acc[5][0], w2.y, sp.x); FMA2(acc[5][1], w2.y, sp.y);
            FMA2(acc[6][0], w3.x, sp.x); FMA2(acc[6][1], w3.x, sp.y);
            FMA2(acc[7][0], w3.y, sp.x); FMA2(acc[7][1], w3.y, sp.y);
        }
    }

    // ---- epilogue: BN fold, +anchor, PReLU, store, row means ----
    #pragma unroll
    for (int oo = 0; oo < 8; oo++) {
        int o = ob + oo;
        float sc = fSc[o], bi = fBi[o], al = aA[o];
        float4 an = *(const float4*)(a_sm + o * NW + p);
        float a0, a1, a2, a3;
        UNPACK2(a0, a1, acc[oo][0]);
        UNPACK2(a2, a3, acc[oo][1]);
        float4 v;
        v.x = fmaf(a0, sc, bi) + an.x;
        v.y = fmaf(a1, sc, bi) + an.y;
        v.z = fmaf(a2, sc, bi) + an.z;
        v.w = fmaf(a3, sc, bi) + an.w;
        v.x = (v.x >= 0.f) ? v.x : al * v.x;
        v.y = (v.y >= 0.f) ? v.y : al * v.y;
        v.z = (v.z >= 0.f) ? v.z : al * v.z;
        v.w = (v.w >= 0.f) ? v.w : al * v.w;
        *(float4*)(g_out + ((size_t)(b * NC + o) * NH + h) * NW + p) = v;

        float ps = v.x + v.y + v.z + v.w;
        #pragma unroll
        for (int s2 = 16; s2 > 0; s2 >>= 1)
            ps += __shfl_xor_sync(0xffffffffu, ps, s2);
        if (lane == 0)
            g_rowmean[(b * NC + o) * NH + h] = ps * (1.0f / NW);
    }
}

// ---------------------------------------------------------------------------
__global__ void k_colmean()
{
    int i = blockIdx.x * blockDim.x + threadIdx.x;   // B*C*W
    if (i >= NB * NC * NW) return;
    int w = i & (NW - 1);
    int bc = i >> 7;
    const float* p = g_out + (size_t)bc * NH * NW + w;
    float s = 0.f;
    #pragma unroll 8
    for (int h = 0; h < NH; h++) s += p[h * NW];
    g_colmean[i] = s * (1.0f / NH);
}

__global__ void k_attn(const float* __restrict__ ca_w1,
                       const float* __restrict__ ca_g, const float* __restrict__ ca_b,
                       const float* __restrict__ ca_m, const float* __restrict__ ca_v,
                       const float* __restrict__ ca_a,
                       const float* __restrict__ ca_wh, const float* __restrict__ ca_ww)
{
    int gw = (blockIdx.x * blockDim.x + threadIdx.x) >> 5;   // one warp per (b, pos)
    int lane = threadIdx.x & 31;
    if (gw >= NB * (NH + NW)) return;
    int b = gw / (NH + NW);
    int pos = gw % (NH + NW);
    bool isH = pos < NH;
    const float* src = isH ? (g_rowmean + (size_t)b * NC * NH + pos)
                           : (g_colmean + (size_t)b * NC * NW + (pos - NH));
    int stride = isH ? NH : NW;

    float m0 = src[lane * stride];
    float m1 = src[(lane + 32) * stride];
    float m2 = src[(lane + 64) * stride];

    float y[8];
    #pragma unroll
    for (int mip = 0; mip < 8; mip++) {
        float z = ca_w1[mip * NC + lane] * m0
                + ca_w1[mip * NC + lane + 32] * m1
                + ca_w1[mip * NC + lane + 64] * m2;
        #pragma unroll
        for (int s2 = 16; s2 > 0; s2 >>= 1)
            z += __shfl_xor_sync(0xffffffffu, z, s2);
        float sc = ca_g[mip] * rsqrtf(ca_v[mip] + EPSV);
        z = (z - ca_m[mip]) * sc + ca_b[mip];
        y[mip] = (z >= 0.f) ? z : ca_a[mip] * z;
    }

    const float* wmat = isH ? ca_wh : ca_ww;
    float* dst = isH ? (g_ah + (size_t)b * NC * NH + pos)
                     : (g_aw + (size_t)b * NC * NW + (pos - NH));
    #pragma unroll
    for (int k = 0; k < 3; k++) {
        int c = lane + k * 32;
        float z = 0.f;
        #pragma unroll
        for (int mip = 0; mip < 8; mip++)
            z += wmat[c * 8 + mip] * y[mip];
        dst[c * stride] = 1.0f / (1.0f + expf(-z));
    }
}

__global__ void k_final(float* __restrict__ out)
{
    int i = blockIdx.x * blockDim.x + threadIdx.x;   // one float4 each
    if (i >= NB * NC * NH * NW / 4) return;
    int w4 = i & (NW / 4 - 1);
    int h  = (i >> 5) & (NH - 1);
    int bc = i >> 12;
    float ah = g_ah[bc * NH + h];
    float4 aw = *(const float4*)(g_aw + bc * NW + w4 * 4);
    float4 v  = *(const float4*)(g_out + (((size_t)bc * NH + h) * NW) + w4 * 4);
    float4 r;
    r.x = v.x * ah * aw.x;
    r.y = v.y * ah * aw.y;
    r.z = v.z * ah * aw.z;
    r.w = v.w * ah * aw.w;
    ((float4*)out)[i] = r;
}

extern "C" void kernel_launch(void* const* d_in, const int* in_sizes, int n_in,
                              void* d_out, int out_size)
{
    const float* x      = (const float*)d_in[0];
    const float* r_m    = (const float*)d_in[1];
    const float* wh_m   = (const float*)d_in[2];
    const float* ww_m   = (const float*)d_in[3];
    const float* r_l    = (const float*)d_in[4];
    const float* wh_l   = (const float*)d_in[5];
    const float* ww_l   = (const float*)d_in[6];
    const float* w_fuse = (const float*)d_in[7];
    const float* bnf_g  = (const float*)d_in[8];
    const float* bnf_b  = (const float*)d_in[9];
    const float* bnf_m  = (const float*)d_in[10];
    const float* bnf_v  = (const float*)d_in[11];
    const float* dg_wh  = (const float*)d_in[12];
    const float* dg_ww  = (const float*)d_in[13];
    const float* dg_g   = (const float*)d_in[14];
    const float* dg_b   = (const float*)d_in[15];
    const float* dg_m   = (const float*)d_in[16];
    const float* dg_v   = (const float*)d_in[17];
    const float* act_a  = (const float*)d_in[18];
    const float* ca_w1  = (const float*)d_in[19];
    const float* ca_g   = (const float*)d_in[20];
    const float* ca_b   = (const float*)d_in[21];
    const float* ca_m   = (const float*)d_in[22];
    const float* ca_v   = (const float*)d_in[23];
    const float* ca_a   = (const float*)d_in[24];
    const float* ca_wh  = (const float*)d_in[25];
    const float* ca_ww  = (const float*)d_in[26];

    const int smem_bytes = SM_FLOATS * (int)sizeof(float);
    cudaFuncSetAttribute(k_main, cudaFuncAttributeMaxDynamicSharedMemorySize, smem_bytes);

    dim3 gv(4, NC, NB);
    k_vert<<<gv, 256>>>(x, r_m, wh_m, r_l, wh_l, dg_wh);

    dim3 g1(NH, NB);
    k_main<<<g1, 384, smem_bytes>>>(x, r_m, ww_m, r_l, ww_l, w_fuse,
                                    bnf_g, bnf_b, bnf_m, bnf_v,
                                    dg_ww, dg_g, dg_b, dg_m, dg_v, act_a);

    k_colmean<<<(NB * NC * NW + 255) / 256, 256>>>();

    k_attn<<<(NB * (NH + NW) * 32 + 255) / 256, 256>>>(ca_w1, ca_g, ca_b, ca_m,
                                                       ca_v, ca_a, ca_wh, ca_ww);

    k_final<<<(NB * NC * NH * NW / 4 + 255) / 256, 256>>>((float*)d_out);
}

// round 5
// speedup vs baseline: 1.8163x; 1.8163x over previous
#include <cuda_runtime.h>

#define NB 8
#define NC 96
#define NH 128
#define NW 128
#define EPSV 1e-5f
#define TW 32
#define HALO 17
#define TWH (TW + 2 * HALO)      // 66
#define WSTR 196                  // duplicated-weight row stride (floats)

// scratch (device globals: no allocation allowed)
__device__ float g_s  [(size_t)NB * NC * NH * NW];   // m + l  (GEMM input)
__device__ float g_anc[(size_t)NB * NC * NH * NW];   // BN-folded anchor
__device__ float g_out[(size_t)NB * NC * NH * NW];
__device__ float g_rowmean[NB * NC * NH];
__device__ float g_colmean[NB * NC * NW];
__device__ float g_ah[NB * NC * NH];
__device__ float g_aw[NB * NC * NW];

#define FMA2(d, a, b) asm("fma.rn.f32x2 %0, %1, %2, %0;" : "+l"(d) : "l"(a), "l"(b))
#define UNPACK2(lo, hi, v) asm("mov.b64 {%0,%1}, %2;" : "=f"(lo), "=f"(hi) : "l"(v))

// ---------------------------------------------------------------------------
// k_elem: per (b, c, w-tile): full axial taps (both axes, merged/dedup'd),
// full anchor (BN-folded). One x read, two writes per element.
// ---------------------------------------------------------------------------
__global__ void __launch_bounds__(256)
k_elem(const float* __restrict__ x,
       const float* __restrict__ r_m, const float* __restrict__ wh_m,
       const float* __restrict__ ww_m,
       const float* __restrict__ r_l, const float* __restrict__ wh_l,
       const float* __restrict__ ww_l,
       const float* __restrict__ dg_wh, const float* __restrict__ dg_ww,
       const float* __restrict__ dg_g,  const float* __restrict__ dg_b,
       const float* __restrict__ dg_m,  const float* __restrict__ dg_v)
{
    __shared__ float xt[NH * TWH];          // 33.8 KB
    __shared__ int   moff[10];
    __shared__ float mfrac[10];
    __shared__ float wmh[10], wmw[10];
    __shared__ float dgh[3], dgw[3];
    __shared__ float s_aSc, s_aBi;
    __shared__ int   snt;

    const int tid = threadIdx.x;
    const int wt  = blockIdx.x;             // 0..3
    const int c   = blockIdx.y;
    const int b   = blockIdx.z;

    if (tid == 0) {
        int mmap[10];
        int nt = 0;
        for (int j = 0; j < 10; j++) {
            float r  = fmaxf((j < 5 ? r_m[0] : r_l[0]), 1.0f);
            int   jo = (j < 5) ? (j - 2) : (j - 7);
            float sh = (float)jo * r;
            float f  = floorf(sh);
            int   off = (int)f;
            float fr  = sh - f;
            int slot = -1;
            for (int s = 0; s < nt; s++)
                if (moff[s] == off && mfrac[s] == fr) { slot = s; break; }
            if (slot < 0) { slot = nt++; moff[slot] = off; mfrac[slot] = fr; }
            mmap[j] = slot;
        }
        snt = nt;
        for (int s = 0; s < nt; s++) { wmh[s] = 0.0f; wmw[s] = 0.0f; }
        for (int j = 0; j < 10; j++) {
            int s = mmap[j];
            if (j < 5) { wmh[s] += wh_m[c * 5 + j];       wmw[s] += ww_m[c * 5 + j]; }
            else       { wmh[s] += wh_l[c * 5 + (j - 5)]; wmw[s] += ww_l[c * 5 + (j - 5)]; }
        }
        dgh[0] = dg_wh[c * 3 + 0]; dgh[1] = dg_wh[c * 3 + 1]; dgh[2] = dg_wh[c * 3 + 2];
        dgw[0] = dg_ww[c * 3 + 0]; dgw[1] = dg_ww[c * 3 + 1]; dgw[2] = dg_ww[c * 3 + 2];
        float sA = dg_g[c] * rsqrtf(dg_v[c] + EPSV);
        s_aSc = sA;
        s_aBi = dg_b[c] - sA * dg_m[c];
    }

    // load 128 x 66 tile (zero-padded halo in w)
    const float* xc0 = x + (size_t)(b * NC + c) * NH * NW;
    const int w0 = wt * TW - HALO;
    for (int i = tid; i < NH * TWH; i += 256) {
        int hh = i / TWH, col = i - hh * TWH;
        int gw = w0 + col;
        xt[i] = ((unsigned)gw < NW) ? xc0[hh * NW + gw] : 0.0f;
    }
    __syncthreads();

    const int nt = snt;
    const float aSc = s_aSc, aBi = s_aBi;
    for (int idx = tid; idx < NH * TW; idx += 256) {
        int h  = idx >> 5;
        int wl = idx & (TW - 1);
        const float* row = xt + h * TWH + HALO;
        float xc = row[wl];
        float sv = 2.0f * xc;
        for (int s = 0; s < nt; s++) {
            int off = moff[s];
            float fr = mfrac[s];
            // vertical
            int hh = h + off;
            float vh = ((unsigned)hh < NH) ? xt[hh * TWH + HALO + wl] : 0.0f;
            // horizontal (halo carries zero padding; offsets beyond halo -> global)
            float vw;
            if (off >= -HALO && off < HALO) {
                vw = row[wl + off];
            } else {
                int gw = wt * TW + wl + off;
                vw = ((unsigned)gw < NW) ? xc0[h * NW + gw] : 0.0f;
            }
            if (fr != 0.0f) {
                float vh2 = ((unsigned)(hh + 1) < NH) ? xt[(hh + 1) * TWH + HALO + wl] : 0.0f;
                float vw2;
                if (off + 1 >= -HALO && off + 1 <= HALO) {
                    vw2 = row[wl + off + 1];
                } else {
                    int gw = wt * TW + wl + off + 1;
                    vw2 = ((unsigned)gw < NW) ? xc0[h * NW + gw] : 0.0f;
                }
                vh = fmaf(fr, vh2 - vh, vh);
                vw = fmaf(fr, vw2 - vw, vw);
            }
            sv = fmaf(wmh[s], vh, sv);
            sv = fmaf(wmw[s], vw, sv);
        }
        // anchor: x + dwconv3_h + dwconv3_w, BN-folded
        float up = (h > 0)      ? xt[(h - 1) * TWH + HALO + wl] : 0.0f;
        float dn = (h < NH - 1) ? xt[(h + 1) * TWH + HALO + wl] : 0.0f;
        float lf = row[wl - 1];
        float rt = row[wl + 1];
        float e = dgh[0] * up + dgh[1] * xc + dgh[2] * dn
                + dgw[0] * lf + dgw[1] * xc + dgw[2] * rt;
        size_t gi = ((size_t)(b * NC + c) * NH + h) * NW + wt * TW + wl;
        g_s[gi]   = sv;
        g_anc[gi] = fmaf(aSc, xc + e, aBi);
    }
}

// ---------------------------------------------------------------------------
// k_main: per (b, h) row: 96(o) x 128(p) x 96(k) GEMM (f32x2) + epilogue
// smem: s_sm 12288 | wbuf 24*196=4704 | fSc/fBi/aA 288  -> ~69 KB
// ---------------------------------------------------------------------------
#define SM_FLOATS (NC * NW + 24 * WSTR + 3 * NC)

__global__ void __launch_bounds__(384)
k_main(const float* __restrict__ w_fuse,
       const float* __restrict__ bnf_g, const float* __restrict__ bnf_b,
       const float* __restrict__ bnf_m, const float* __restrict__ bnf_v,
       const float* __restrict__ act_a)
{
    extern __shared__ float sm[];
    float* s_sm = sm;
    float* wbuf = sm + NC * NW;
    float* fSc  = sm + NC * NW + 24 * WSTR;
    float* fBi  = fSc + NC;
    float* aA   = fBi + NC;

    const int tid = threadIdx.x;
    const int b = blockIdx.y;
    const int h = blockIdx.x;

    if (tid < NC) {
        float sF = bnf_g[tid] * rsqrtf(bnf_v[tid] + EPSV);
        fSc[tid] = sF;
        fBi[tid] = bnf_b[tid] - sF * bnf_m[tid];
        aA[tid]  = act_a[tid];
    }
    // stage s row for all channels (float4, coalesced)
    for (int i = tid; i < NC * NW / 4; i += 384) {
        int ci = i >> 5, w4 = i & 31;
        ((float4*)s_sm)[i] =
            ((const float4*)g_s)[((size_t)(b * NC + ci) * NH + h) * (NW / 4) + w4];
    }

    const int lane = tid & 31;
    const int warp = tid >> 5;        // 12 warps, 8 outputs each
    const int ob = warp * 8;
    const int p = lane * 4;

    unsigned long long acc[8][2];
    #pragma unroll
    for (int i = 0; i < 8; i++) { acc[i][0] = 0ull; acc[i][1] = 0ull; }

    for (int c0 = 0; c0 < NC; c0 += 24) {
        __syncthreads();   // prior wbuf consumers done (and s_sm ready on first pass)
        for (int i = tid; i < 24 * NC; i += 384) {
            int cl = i % 24, o = i / 24;
            float v = w_fuse[o * NC + c0 + cl];
            wbuf[cl * WSTR + 2 * o]     = v;   // duplicated pair for f32x2
            wbuf[cl * WSTR + 2 * o + 1] = v;
        }
        __syncthreads();
        #pragma unroll
        for (int cl = 0; cl < 24; cl++) {
            ulonglong2 sp = *(const ulonglong2*)(s_sm + (c0 + cl) * NW + p);
            const ulonglong2* wq = (const ulonglong2*)(wbuf + cl * WSTR + 2 * ob);
            ulonglong2 w0 = wq[0], w1 = wq[1], w2 = wq[2], w3 = wq[3];
            FMA2(acc[0][0], w0.x, sp.x); FMA2(acc[0][1], w0.x, sp.y);
            FMA2(acc[1][0], w0.y, sp.x); FMA2(acc[1][1], w0.y, sp.y);
            FMA2(acc[2][0], w1.x, sp.x); FMA2(acc[2][1], w1.x, sp.y);
            FMA2(acc[3][0], w1.y, sp.x); FMA2(acc[3][1], w1.y, sp.y);
            FMA2(acc[4][0], w2.x, sp.x); FMA2(acc[4][1], w2.x, sp.y);
            FMA2(acc[5][0], w2.y, sp.x); FMA2(acc[5][1], w2.y, sp.y);
            FMA2(acc[6][0], w3.x, sp.x); FMA2(acc[6][1], w3.x, sp.y);
            FMA2(acc[7][0], w3.y, sp.x); FMA2(acc[7][1], w3.y, sp.y);
        }
    }

    // ---- epilogue: BN fold, +anchor (global, coalesced), PReLU, store, row means ----
    #pragma unroll
    for (int oo = 0; oo < 8; oo++) {
        int o = ob + oo;
        float sc = fSc[o], bi = fBi[o], al = aA[o];
        size_t gbase = ((size_t)(b * NC + o) * NH + h) * NW + p;
        float4 an = *(const float4*)(g_anc + gbase);
        float a0, a1, a2, a3;
        UNPACK2(a0, a1, acc[oo][0]);
        UNPACK2(a2, a3, acc[oo][1]);
        float4 v;
        v.x = fmaf(a0, sc, bi) + an.x;
        v.y = fmaf(a1, sc, bi) + an.y;
        v.z = fmaf(a2, sc, bi) + an.z;
        v.w = fmaf(a3, sc, bi) + an.w;
        v.x = (v.x >= 0.f) ? v.x : al * v.x;
        v.y = (v.y >= 0.f) ? v.y : al * v.y;
        v.z = (v.z >= 0.f) ? v.z : al * v.z;
        v.w = (v.w >= 0.f) ? v.w : al * v.w;
        *(float4*)(g_out + gbase) = v;

        float ps = v.x + v.y + v.z + v.w;
        #pragma unroll
        for (int s2 = 16; s2 > 0; s2 >>= 1)
            ps += __shfl_xor_sync(0xffffffffu, ps, s2);
        if (lane == 0)
            g_rowmean[(b * NC + o) * NH + h] = ps * (1.0f / NW);
    }
}

// ---------------------------------------------------------------------------
__global__ void k_colmean()
{
    int i = blockIdx.x * blockDim.x + threadIdx.x;   // B*C*W
    if (i >= NB * NC * NW) return;
    int w = i & (NW - 1);
    int bc = i >> 7;
    const float* p = g_out + (size_t)bc * NH * NW + w;
    float s = 0.f;
    #pragma unroll 8
    for (int h = 0; h < NH; h++) s += p[h * NW];
    g_colmean[i] = s * (1.0f / NH);
}

__global__ void k_attn(const float* __restrict__ ca_w1,
                       const float* __restrict__ ca_g, const float* __restrict__ ca_b,
                       const float* __restrict__ ca_m, const float* __restrict__ ca_v,
                       const float* __restrict__ ca_a,
                       const float* __restrict__ ca_wh, const float* __restrict__ ca_ww)
{
    int gw = (blockIdx.x * blockDim.x + threadIdx.x) >> 5;   // one warp per (b, pos)
    int lane = threadIdx.x & 31;
    if (gw >= NB * (NH + NW)) return;
    int b = gw / (NH + NW);
    int pos = gw % (NH + NW);
    bool isH = pos < NH;
    const float* src = isH ? (g_rowmean + (size_t)b * NC * NH + pos)
                           : (g_colmean + (size_t)b * NC * NW + (pos - NH));
    int stride = isH ? NH : NW;

    float m0 = src[lane * stride];
    float m1 = src[(lane + 32) * stride];
    float m2 = src[(lane + 64) * stride];

    float y[8];
    #pragma unroll
    for (int mip = 0; mip < 8; mip++) {
        float z = ca_w1[mip * NC + lane] * m0
                + ca_w1[mip * NC + lane + 32] * m1
                + ca_w1[mip * NC + lane + 64] * m2;
        #pragma unroll
        for (int s2 = 16; s2 > 0; s2 >>= 1)
            z += __shfl_xor_sync(0xffffffffu, z, s2);
        float sc = ca_g[mip] * rsqrtf(ca_v[mip] + EPSV);
        z = (z - ca_m[mip]) * sc + ca_b[mip];
        y[mip] = (z >= 0.f) ? z : ca_a[mip] * z;
    }

    const float* wmat = isH ? ca_wh : ca_ww;
    float* dst = isH ? (g_ah + (size_t)b * NC * NH + pos)
                     : (g_aw + (size_t)b * NC * NW + (pos - NH));
    #pragma unroll
    for (int k = 0; k < 3; k++) {
        int c = lane + k * 32;
        float z = 0.f;
        #pragma unroll
        for (int mip = 0; mip < 8; mip++)
            z += wmat[c * 8 + mip] * y[mip];
        dst[c * stride] = 1.0f / (1.0f + expf(-z));
    }
}

__global__ void k_final(float* __restrict__ out)
{
    int i = blockIdx.x * blockDim.x + threadIdx.x;   // one float4 each
    if (i >= NB * NC * NH * NW / 4) return;
    int w4 = i & (NW / 4 - 1);
    int h  = (i >> 5) & (NH - 1);
    int bc = i >> 12;
    float ah = g_ah[bc * NH + h];
    float4 aw = *(const float4*)(g_aw + bc * NW + w4 * 4);
    float4 v  = *(const float4*)(g_out + (((size_t)bc * NH + h) * NW) + w4 * 4);
    float4 r;
    r.x = v.x * ah * aw.x;
    r.y = v.y * ah * aw.y;
    r.z = v.z * ah * aw.z;
    r.w = v.w * ah * aw.w;
    ((float4*)out)[i] = r;
}

extern "C" void kernel_launch(void* const* d_in, const int* in_sizes, int n_in,
                              void* d_out, int out_size)
{
    const float* x      = (const float*)d_in[0];
    const float* r_m    = (const float*)d_in[1];
    const float* wh_m   = (const float*)d_in[2];
    const float* ww_m   = (const float*)d_in[3];
    const float* r_l    = (const float*)d_in[4];
    const float* wh_l   = (const float*)d_in[5];
    const float* ww_l   = (const float*)d_in[6];
    const float* w_fuse = (const float*)d_in[7];
    const float* bnf_g  = (const float*)d_in[8];
    const float* bnf_b  = (const float*)d_in[9];
    const float* bnf_m  = (const float*)d_in[10];
    const float* bnf_v  = (const float*)d_in[11];
    const float* dg_wh  = (const float*)d_in[12];
    const float* dg_ww  = (const float*)d_in[13];
    const float* dg_g   = (const float*)d_in[14];
    const float* dg_b   = (const float*)d_in[15];
    const float* dg_m   = (const float*)d_in[16];
    const float* dg_v   = (const float*)d_in[17];
    const float* act_a  = (const float*)d_in[18];
    const float* ca_w1  = (const float*)d_in[19];
    const float* ca_g   = (const float*)d_in[20];
    const float* ca_b   = (const float*)d_in[21];
    const float* ca_m   = (const float*)d_in[22];
    const float* ca_v   = (const float*)d_in[23];
    const float* ca_a   = (const float*)d_in[24];
    const float* ca_wh  = (const float*)d_in[25];
    const float* ca_ww  = (const float*)d_in[26];

    const int smem_bytes = SM_FLOATS * (int)sizeof(float);
    cudaFuncSetAttribute(k_main, cudaFuncAttributeMaxDynamicSharedMemorySize, smem_bytes);

    dim3 ge(4, NC, NB);
    k_elem<<<ge, 256>>>(x, r_m, wh_m, ww_m, r_l, wh_l, ww_l,
                        dg_wh, dg_ww, dg_g, dg_b, dg_m, dg_v);

    dim3 g1(NH, NB);
    k_main<<<g1, 384, smem_bytes>>>(w_fuse, bnf_g, bnf_b, bnf_m, bnf_v, act_a);

    k_colmean<<<(NB * NC * NW + 255) / 256, 256>>>();

    k_attn<<<(NB * (NH + NW) * 32 + 255) / 256, 256>>>(ca_w1, ca_g, ca_b, ca_m,
                                                       ca_v, ca_a, ca_wh, ca_ww);

    k_final<<<(NB * NC * NH * NW / 4 + 255) / 256, 256>>>((float*)d_out);
}

// round 7
// speedup vs baseline: 2.1573x; 1.1877x over previous
#include <cuda_runtime.h>

#define NB 8
#define NC 96
#define NH 128
#define NW 128
#define EPSV 1e-5f

// k_elem tile geometry
#define TW2 64
#define VH 17
#define WH 17
#define TR (NH + 2 * VH)      // 162
#define TC (TW2 + 2 * WH)     // 98

#define WSTR 196              // duplicated-weight row stride (floats)

// ---- scratch (device globals: no allocation allowed) ----
__device__ float g_s  [(size_t)NB * NC * NH * NW];
__device__ float g_anc[(size_t)NB * NC * NH * NW];
__device__ float g_out[(size_t)NB * NC * NH * NW];
__device__ float g_rmT[NB * NH * NC];     // [b][h][c]
__device__ float g_cmT[NB * NW * NC];     // [b][w][c]
__device__ float g_ah[NB * NC * NH];
__device__ float g_aw[NB * NC * NW];

// setup outputs
__device__ int   g_moff[10];
__device__ float g_mfrac[10];
__device__ int   g_nt;
__device__ int   g_fast;                  // 1 iff all |off|<=16 and all frac==0
__device__ float g_wmh[NC][10], g_wmw[NC][10];
__device__ float g_dgh[NC][3],  g_dgw[NC][3];
__device__ float g_aSc[NC], g_aBi[NC];
__device__ float g_fSc[NC], g_fBi[NC], g_aA[NC];

#define FMA2(d, a, b) asm("fma.rn.f32x2 %0, %1, %2, %0;" : "+l"(d) : "l"(a), "l"(b))
#define UNPACK2(lo, hi, v) asm("mov.b64 {%0,%1}, %2;" : "=f"(lo), "=f"(hi) : "l"(v))

// ---------------------------------------------------------------------------
// k_setup: one block, 96 threads. Merged taps + folded BN params.
// ---------------------------------------------------------------------------
__global__ void k_setup(const float* __restrict__ r_m,  const float* __restrict__ wh_m,
                        const float* __restrict__ ww_m,
                        const float* __restrict__ r_l,  const float* __restrict__ wh_l,
                        const float* __restrict__ ww_l,
                        const float* __restrict__ dg_wh, const float* __restrict__ dg_ww,
                        const float* __restrict__ dg_g,  const float* __restrict__ dg_b,
                        const float* __restrict__ dg_m,  const float* __restrict__ dg_v,
                        const float* __restrict__ bnf_g, const float* __restrict__ bnf_b,
                        const float* __restrict__ bnf_m, const float* __restrict__ bnf_v,
                        const float* __restrict__ act_a)
{
    __shared__ int   map[10];
    __shared__ int   moff_s[10];
    __shared__ float mfrac_s[10];
    const int tid = threadIdx.x;

    if (tid == 0) {
        int nt = 0;
        int fast = 1;
        for (int j = 0; j < 10; j++) {
            float r  = fmaxf((j < 5 ? r_m[0] : r_l[0]), 1.0f);
            int   jo = (j < 5) ? (j - 2) : (j - 7);
            float sh = (float)jo * r;
            float f  = floorf(sh);
            int   off = (int)f;
            float fr  = sh - f;
            int slot = -1;
            for (int s = 0; s < nt; s++)
                if (moff_s[s] == off && mfrac_s[s] == fr) { slot = s; break; }
            if (slot < 0) { slot = nt++; moff_s[slot] = off; mfrac_s[slot] = fr; }
            map[j] = slot;
            if (off < -16 || off > 16 || fr != 0.0f) fast = 0;
        }
        for (int s = nt; s < 10; s++) { moff_s[s] = 0; mfrac_s[s] = 0.0f; }
        g_nt = nt;
        g_fast = fast;
        for (int s = 0; s < 10; s++) { g_moff[s] = moff_s[s]; g_mfrac[s] = mfrac_s[s]; }
    }
    __syncthreads();

    int c = tid;
    if (c < NC) {
        float wh[10], ww[10];
        #pragma unroll
        for (int s = 0; s < 10; s++) { wh[s] = 0.0f; ww[s] = 0.0f; }
        for (int j = 0; j < 10; j++) {
            int s = map[j];
            if (j < 5) { wh[s] += wh_m[c * 5 + j];       ww[s] += ww_m[c * 5 + j]; }
            else       { wh[s] += wh_l[c * 5 + (j - 5)]; ww[s] += ww_l[c * 5 + (j - 5)]; }
        }
        #pragma unroll
        for (int s = 0; s < 10; s++) { g_wmh[c][s] = wh[s]; g_wmw[c][s] = ww[s]; }
        for (int k = 0; k < 3; k++) { g_dgh[c][k] = dg_wh[c * 3 + k]; g_dgw[c][k] = dg_ww[c * 3 + k]; }
        float sA = dg_g[c] * rsqrtf(dg_v[c] + EPSV);
        g_aSc[c] = sA;
        g_aBi[c] = dg_b[c] - sA * dg_m[c];
        float sF = bnf_g[c] * rsqrtf(bnf_v[c] + EPSV);
        g_fSc[c] = sF;
        g_fBi[c] = bnf_b[c] - sF * bnf_m[c];
        g_aA[c]  = act_a[c];
    }
}

// ---------------------------------------------------------------------------
// k_elem: per (b, c, w-tile): s = m+l and BN-folded anchor.
// Zero-padded halo tile in both axes -> hot path has no bounds checks.
// ---------------------------------------------------------------------------
__global__ void __launch_bounds__(256, 3)
k_elem(const float* __restrict__ x)
{
    extern __shared__ float xt[];                 // TR * TC floats
    __shared__ float wmh[10], wmw[10];
    __shared__ int   moff_l[10];
    __shared__ float mfrac_l[10];
    __shared__ float sdg[8];                      // dgh0..2, dgw0..2, aSc, aBi
    __shared__ int   s_fast, s_nt;

    const int tid = threadIdx.x;
    const int wt  = blockIdx.x;                   // 0..1
    const int c   = blockIdx.y;
    const int b   = blockIdx.z;

    if (tid < 10) {
        moff_l[tid]  = g_moff[tid];
        mfrac_l[tid] = g_mfrac[tid];
        wmh[tid] = g_wmh[c][tid];
        wmw[tid] = g_wmw[c][tid];
    }
    if (tid == 0) {
        s_fast = g_fast;
        s_nt   = g_nt;
        sdg[0] = g_dgh[c][0]; sdg[1] = g_dgh[c][1]; sdg[2] = g_dgh[c][2];
        sdg[3] = g_dgw[c][0]; sdg[4] = g_dgw[c][1]; sdg[5] = g_dgw[c][2];
        sdg[6] = g_aSc[c];    sdg[7] = g_aBi[c];
    }

    const float* xc0 = x + (size_t)(b * NC + c) * NH * NW;
    const int w0 = wt * TW2 - WH;

    for (int i = tid; i < TR * TC; i += 256) {
        int rr = i / TC, cc = i - rr * TC;
        int gh = rr - VH, gw = w0 + cc;
        xt[i] = ((unsigned)gh < NH && (unsigned)gw < NW) ? xc0[gh * NW + gw] : 0.0f;
    }
    __syncthreads();

    const float dgh0 = sdg[0], dgh1 = sdg[1], dgh2 = sdg[2];
    const float dgw0 = sdg[3], dgw1 = sdg[4], dgw2 = sdg[5];
    const float aSc = sdg[6], aBi = sdg[7];
    const size_t gb = (size_t)(b * NC + c) * NH * NW + wt * TW2;

    if (s_fast) {
        float rwh[10], rww[10];
        int   rvo[10], rho[10];
        #pragma unroll
        for (int s = 0; s < 10; s++) {
            rwh[s] = wmh[s]; rww[s] = wmw[s];
            rho[s] = moff_l[s];
            rvo[s] = moff_l[s] * TC;
        }
        for (int idx = tid; idx < NH * TW2; idx += 256) {
            int h  = idx >> 6;
            int wl = idx & (TW2 - 1);
            const float* ctr = xt + (h + VH) * TC + (WH + wl);
            float xc = ctr[0];
            float sv = 2.0f * xc;
            #pragma unroll
            for (int s = 0; s < 10; s++) {
                sv = fmaf(rwh[s], ctr[rvo[s]], sv);
                sv = fmaf(rww[s], ctr[rho[s]], sv);
            }
            float e = dgh0 * ctr[-TC] + dgh1 * xc + dgh2 * ctr[TC]
                    + dgw0 * ctr[-1]  + dgw1 * xc + dgw2 * ctr[1];
            size_t gi = gb + (size_t)h * NW + wl;
            g_s[gi]   = sv;
            g_anc[gi] = fmaf(aSc, xc + e, aBi);
        }
    } else {
        // generic fallback: guarded global reads (any offset / fraction)
        const int nt = s_nt;
        for (int idx = tid; idx < NH * TW2; idx += 256) {
            int h  = idx >> 6;
            int wl = idx & (TW2 - 1);
            int gw = wt * TW2 + wl;
            float xc = xc0[h * NW + gw];
            float sv = 2.0f * xc;
            for (int s = 0; s < nt; s++) {
                int off = moff_l[s];
                float fr = mfrac_l[s];
                int hh = h + off, wp = gw + off;
                float vh = ((unsigned)hh < NH) ? xc0[hh * NW + gw] : 0.0f;
                float vw = ((unsigned)wp < NW) ? xc0[h * NW + wp] : 0.0f;
                if (fr != 0.0f) {
                    float vh2 = ((unsigned)(hh + 1) < NH) ? xc0[(hh + 1) * NW + gw] : 0.0f;
                    float vw2 = ((unsigned)(wp + 1) < NW) ? xc0[h * NW + wp + 1] : 0.0f;
                    vh = fmaf(fr, vh2 - vh, vh);
                    vw = fmaf(fr, vw2 - vw, vw);
                }
                sv = fmaf(wmh[s], vh, sv);
                sv = fmaf(wmw[s], vw, sv);
            }
            float up = (h > 0)      ? xc0[(h - 1) * NW + gw] : 0.0f;
            float dn = (h < NH - 1) ? xc0[(h + 1) * NW + gw] : 0.0f;
            float lf = (gw > 0)     ? xc0[h * NW + gw - 1]   : 0.0f;
            float rt = (gw < NW - 1)? xc0[h * NW + gw + 1]   : 0.0f;
            float e = dgh0 * up + dgh1 * xc + dgh2 * dn
                    + dgw0 * lf + dgw1 * xc + dgw2 * rt;
            size_t gi = gb + (size_t)h * NW + wl;
            g_s[gi]   = sv;
            g_anc[gi] = fmaf(aSc, xc + e, aBi);
        }
    }
}

// ---------------------------------------------------------------------------
// k_main: persistent; weights resident in smem once; 4 rows per block.
// smem: wbuf 96*196 | fSc/fBi/aA 288  -> 76,416 B
// ---------------------------------------------------------------------------
#define KM_SM_FLOATS (NC * WSTR + 3 * NC)
#define KM_GRID 256

__global__ void __launch_bounds__(384, 2)
k_main(const float* __restrict__ w_fuse)
{
    extern __shared__ float sm[];
    float* wbuf = sm;
    float* fSc  = sm + NC * WSTR;
    float* fBi  = fSc + NC;
    float* aA   = fBi + NC;

    const int tid = threadIdx.x;

    for (int i = tid; i < NC * NC; i += 384) {
        int o = i / NC, cl = i - o * NC;
        float v = w_fuse[i];
        wbuf[cl * WSTR + 2 * o]     = v;
        wbuf[cl * WSTR + 2 * o + 1] = v;
    }
    if (tid < NC) { fSc[tid] = g_fSc[tid]; fBi[tid] = g_fBi[tid]; aA[tid] = g_aA[tid]; }
    __syncthreads();

    const int lane = tid & 31;
    const int warp = tid >> 5;          // 12 warps, 8 outputs each
    const int ob = warp * 8;
    const int p = lane * 4;

    for (int row = blockIdx.x; row < NB * NH; row += KM_GRID) {
        int b = row >> 7, h = row & (NH - 1);
        const float* srow = g_s + ((size_t)b * NC * NH + h) * NW;

        unsigned long long acc[8][2];
        #pragma unroll
        for (int i = 0; i < 8; i++) { acc[i][0] = 0ull; acc[i][1] = 0ull; }

        #pragma unroll 4
        for (int cl = 0; cl < NC; cl++) {
            ulonglong2 sp = *(const ulonglong2*)(srow + (size_t)cl * NH * NW + p);
            const ulonglong2* wq = (const ulonglong2*)(wbuf + cl * WSTR + 2 * ob);
            ulonglong2 w0 = wq[0], w1 = wq[1], w2 = wq[2], w3 = wq[3];
            FMA2(acc[0][0], w0.x, sp.x); FMA2(acc[0][1], w0.x, sp.y);
            FMA2(acc[1][0], w0.y, sp.x); FMA2(acc[1][1], w0.y, sp.y);
            FMA2(acc[2][0], w1.x, sp.x); FMA2(acc[2][1], w1.x, sp.y);
            FMA2(acc[3][0], w1.y, sp.x); FMA2(acc[3][1], w1.y, sp.y);
            FMA2(acc[4][0], w2.x, sp.x); FMA2(acc[4][1], w2.x, sp.y);
            FMA2(acc[5][0], w2.y, sp.x); FMA2(acc[5][1], w2.y, sp.y);
            FMA2(acc[6][0], w3.x, sp.x); FMA2(acc[6][1], w3.x, sp.y);
            FMA2(acc[7][0], w3.y, sp.x); FMA2(acc[7][1], w3.y, sp.y);
        }

        #pragma unroll
        for (int oo = 0; oo < 8; oo++) {
            int o = ob + oo;
            float sc = fSc[o], bi = fBi[o], al = aA[o];
            size_t gbase = ((size_t)(b * NC + o) * NH + h) * NW + p;
            float4 an = *(const float4*)(g_anc + gbase);
            float a0, a1, a2, a3;
            UNPACK2(a0, a1, acc[oo][0]);
            UNPACK2(a2, a3, acc[oo][1]);
            float4 v;
            v.x = fmaf(a0, sc, bi) + an.x;
            v.y = fmaf(a1, sc, bi) + an.y;
            v.z = fmaf(a2, sc, bi) + an.z;
            v.w = fmaf(a3, sc, bi) + an.w;
            v.x = (v.x >= 0.f) ? v.x : al * v.x;
            v.y = (v.y >= 0.f) ? v.y : al * v.y;
            v.z = (v.z >= 0.f) ? v.z : al * v.z;
            v.w = (v.w >= 0.f) ? v.w : al * v.w;
            *(float4*)(g_out + gbase) = v;

            float ps = v.x + v.y + v.z + v.w;
            #pragma unroll
            for (int s2 = 16; s2 > 0; s2 >>= 1)
                ps += __shfl_xor_sync(0xffffffffu, ps, s2);
            if (lane == 0)
                g_rmT[((size_t)b * NH + h) * NC + o] = ps * (1.0f / NW);
        }
    }
}

// ---------------------------------------------------------------------------
__global__ void k_colmean()
{
    int i = blockIdx.x * blockDim.x + threadIdx.x;   // B*C*W
    if (i >= NB * NC * NW) return;
    int w = i & (NW - 1);
    int bc = i >> 7;
    int c = bc % NC, b = bc / NC;
    const float* p = g_out + (size_t)bc * NH * NW + w;
    float s = 0.f;
    #pragma unroll 8
    for (int h = 0; h < NH; h++) s += p[h * NW];
    g_cmT[((size_t)b * NW + w) * NC + c] = s * (1.0f / NH);
}

__global__ void k_attn(const float* __restrict__ ca_w1,
                       const float* __restrict__ ca_g, const float* __restrict__ ca_b,
                       const float* __restrict__ ca_m, const float* __restrict__ ca_v,
                       const float* __restrict__ ca_a,
                       const float* __restrict__ ca_wh, const float* __restrict__ ca_ww)
{
    int gw = (blockIdx.x * blockDim.x + threadIdx.x) >> 5;   // one warp per (b, pos)
    int lane = threadIdx.x & 31;
    if (gw >= NB * (NH + NW)) return;
    int b = gw / (NH + NW);
    int pos = gw % (NH + NW);
    bool isH = pos < NH;
    const float* src = isH ? (g_rmT + ((size_t)b * NH + pos) * NC)
                           : (g_cmT + ((size_t)b * NW + (pos - NH)) * NC);

    float m0 = src[lane];
    float m1 = src[lane + 32];
    float m2 = src[lane + 64];

    float y[8];
    #pragma unroll
    for (int mip = 0; mip < 8; mip++) {
        float z = ca_w1[mip * NC + lane] * m0
                + ca_w1[mip * NC + lane + 32] * m1
                + ca_w1[mip * NC + lane + 64] * m2;
        #pragma unroll
        for (int s2 = 16; s2 > 0; s2 >>= 1)
            z += __shfl_xor_sync(0xffffffffu, z, s2);
        float sc = ca_g[mip] * rsqrtf(ca_v[mip] + EPSV);
        z = (z - ca_m[mip]) * sc + ca_b[mip];
        y[mip] = (z >= 0.f) ? z : ca_a[mip] * z;
    }

    const float* wmat = isH ? ca_wh : ca_ww;
    int stride = isH ? NH : NW;
    float* dst = isH ? (g_ah + (size_t)b * NC * NH + pos)
                     : (g_aw + (size_t)b * NC * NW + (pos - NH));
    #pragma unroll
    for (int k = 0; k < 3; k++) {
        int c = lane + k * 32;
        float z = 0.f;
        #pragma unroll
        for (int mip = 0; mip < 8; mip++)
            z += wmat[c * 8 + mip] * y[mip];
        dst[c * stride] = 1.0f / (1.0f + expf(-z));
    }
}

__global__ void k_final(float* __restrict__ out)
{
    int i = blockIdx.x * blockDim.x + threadIdx.x;   // one float4 each
    if (i >= NB * NC * NH * NW / 4) return;
    int w4 = i & (NW / 4 - 1);
    int h  = (i >> 5) & (NH - 1);
    int bc = i >> 12;
    float ah = g_ah[bc * NH + h];
    float4 aw = *(const float4*)(g_aw + bc * NW + w4 * 4);
    float4 v  = *(const float4*)(g_out + (((size_t)bc * NH + h) * NW) + w4 * 4);
    float4 r;
    r.x = v.x * ah * aw.x;
    r.y = v.y * ah * aw.y;
    r.z = v.z * ah * aw.z;
    r.w = v.w * ah * aw.w;
    ((float4*)out)[i] = r;
}

extern "C" void kernel_launch(void* const* d_in, const int* in_sizes, int n_in,
                              void* d_out, int out_size)
{
    const float* x      = (const float*)d_in[0];
    const float* r_m    = (const float*)d_in[1];
    const float* wh_m   = (const float*)d_in[2];
    const float* ww_m   = (const float*)d_in[3];
    const float* r_l    = (const float*)d_in[4];
    const float* wh_l   = (const float*)d_in[5];
    const float* ww_l   = (const float*)d_in[6];
    const float* w_fuse = (const float*)d_in[7];
    const float* bnf_g  = (const float*)d_in[8];
    const float* bnf_b  = (const float*)d_in[9];
    const float* bnf_m  = (const float*)d_in[10];
    const float* bnf_v  = (const float*)d_in[11];
    const float* dg_wh  = (const float*)d_in[12];
    const float* dg_ww  = (const float*)d_in[13];
    const float* dg_g   = (const float*)d_in[14];
    const float* dg_b   = (const float*)d_in[15];
    const float* dg_m   = (const float*)d_in[16];
    const float* dg_v   = (const float*)d_in[17];
    const float* act_a  = (const float*)d_in[18];
    const float* ca_w1  = (const float*)d_in[19];
    const float* ca_g   = (const float*)d_in[20];
    const float* ca_b   = (const float*)d_in[21];
    const float* ca_m   = (const float*)d_in[22];
    const float* ca_v   = (const float*)d_in[23];
    const float* ca_a   = (const float*)d_in[24];
    const float* ca_wh  = (const float*)d_in[25];
    const float* ca_ww  = (const float*)d_in[26];

    k_setup<<<1, 96>>>(r_m, wh_m, ww_m, r_l, wh_l, ww_l,
                       dg_wh, dg_ww, dg_g, dg_b, dg_m, dg_v,
                       bnf_g, bnf_b, bnf_m, bnf_v, act_a);

    const int elem_smem = TR * TC * (int)sizeof(float);
    cudaFuncSetAttribute(k_elem, cudaFuncAttributeMaxDynamicSharedMemorySize, elem_smem);
    dim3 ge(NW / TW2, NC, NB);
    k_elem<<<ge, 256, elem_smem>>>(x);

    const int main_smem = KM_SM_FLOATS * (int)sizeof(float);
    cudaFuncSetAttribute(k_main, cudaFuncAttributeMaxDynamicSharedMemorySize, main_smem);
    k_main<<<KM_GRID, 384, main_smem>>>(w_fuse);

    k_colmean<<<(NB * NC * NW + 255) / 256, 256>>>();

    k_attn<<<(NB * (NH + NW) * 32 + 255) / 256, 256>>>(ca_w1, ca_g, ca_b, ca_m,
                                                       ca_v, ca_a, ca_wh, ca_ww);

    k_final<<<(NB * NC * NH * NW / 4 + 255) / 256, 256>>>((float*)d_out);
}